// round 15
// baseline (speedup 1.0000x reference)
#include <cuda_runtime.h>
#include <cuda_fp16.h>
#include <cstdint>

#define C 128
#define NMAX 50176
#define EMAX 800000

// ---------------- device scratch ----------------
__device__ float g_P1[NMAX * C];
__device__ float g_QK[NMAX * C];
__device__ float g_KK[NMAX * C];
__device__ float g_v[NMAX * C];
__device__ float g_z[NMAX * C];
__device__ float g_num[NMAX * C];
__device__ float g_Wq[C * C];
__device__ float g_Wk[C * C];
__device__ int g_src[EMAX];
__device__ int g_dst[EMAX];
__device__ int g_src2[EMAX];   // sorted by dst
__device__ int g_dst2[EMAX];
__device__ int g_cnt[NMAX];    // histogram -> cursor (re-zeroed by out_kernel)
__device__ __half g_B1h[C * C];
__device__ __half g_B2h[C * C];
__device__ __half g_B3h[C * C];

// ---------------- mma helpers ----------------
__device__ __forceinline__ uint32_t smem_u32(const void* p) {
    uint32_t a;
    asm("{ .reg .u64 t; cvta.to.shared.u64 t, %1; cvt.u32.u64 %0, t; }" : "=r"(a) : "l"(p));
    return a;
}
__device__ __forceinline__ void ldsm_x4(uint32_t addr, uint32_t& r0, uint32_t& r1,
                                        uint32_t& r2, uint32_t& r3) {
    asm volatile("ldmatrix.sync.aligned.m8n8.x4.shared.b16 {%0,%1,%2,%3}, [%4];"
                 : "=r"(r0), "=r"(r1), "=r"(r2), "=r"(r3) : "r"(addr));
}
__device__ __forceinline__ void mma_16816(float* acc, uint32_t a0, uint32_t a1,
                                          uint32_t a2, uint32_t a3,
                                          uint32_t b0, uint32_t b1) {
    asm volatile(
        "mma.sync.aligned.m16n8k16.row.col.f32.f16.f16.f32 "
        "{%0,%1,%2,%3}, {%4,%5,%6,%7}, {%8,%9}, {%0,%1,%2,%3};"
        : "+f"(acc[0]), "+f"(acc[1]), "+f"(acc[2]), "+f"(acc[3])
        : "r"(a0), "r"(a1), "r"(a2), "r"(a3), "r"(b0), "r"(b1));
}
#define PF_L2(ptr) asm volatile("prefetch.global.L2 [%0];" :: "l"(ptr))

// smem layout (bytes). fp16 tiles rows padded to 272B.
#define ROWB 272
#define OFF_A0 0               // 34816; reused as staging (hf=1) post-GEMM3
#define OFF_A1 34816           // 34816
#define OFF_IDX 69632          // 1024
#define OFF_BIAS 70656         // 2048
#define OFF_S2 72704           // 34816; fp32 staging (hf=0)
#define SZE 107520

// ---------------- launch 0: convert (dtype detect) + histogram ----------------
__global__ void convert_hist_kernel(const void* __restrict__ ei, long long E, int n) {
    __shared__ int s_is64;
    if (threadIdx.x == 0) {
        const long long* p = (const long long*)ei;
        int ok64 = 1;
        int lim = (E < 64) ? (int)E : 64;
        for (int i = 0; i < lim; i++) {
            long long v = p[i];
            if (v < 0 || v >= n) { ok64 = 0; break; }
        }
        s_is64 = ok64;
    }
    __syncthreads();
    long long i = (long long)blockIdx.x * blockDim.x + threadIdx.x;
    if (i >= E) return;
    int s, d;
    if (s_is64) {
        const long long* p = (const long long*)ei;
        s = (int)p[i];
        d = (int)p[E + i];
    } else {
        const int* p = (const int*)ei;
        s = p[i];
        d = p[E + i];
    }
    g_src[i] = s;
    g_dst[i] = d;
    atomicAdd(&g_cnt[d], 1);
}

// ---------------- launch 1: scan (block 0) + util (blocks 1..) ----------------
__global__ void scan_util_kernel(const float* __restrict__ Wdst, const float* __restrict__ Wsrc,
                                 const float* __restrict__ att_w1,
                                 const float* __restrict__ w1, const float* __restrict__ w2,
                                 const float* __restrict__ w3, int n) {
    if (blockIdx.x == 0) {
        __shared__ int part[256];
        int t = threadIdx.x;
        int chunk = (n + 255) / 256;
        int lo = t * chunk;
        int hi = lo + chunk; if (hi > n) hi = n;
        int s = 0;
        for (int i = lo; i < hi; i++) s += g_cnt[i];
        part[t] = s;
        __syncthreads();
        for (int d = 1; d < 256; d <<= 1) {
            int v = (t >= d) ? part[t - d] : 0;
            __syncthreads();
            part[t] += v;
            __syncthreads();
        }
        int excl = (t == 0) ? 0 : part[t - 1];
        for (int i = lo; i < hi; i++) {
            int c = g_cnt[i];
            g_cnt[i] = excl;
            excl += c;
        }
        return;
    }
    int bid = blockIdx.x - 1;
    int total = n * C;
    for (int i = (bid * 256 + threadIdx.x) * 4; i < total; i += 511 * 256 * 4) {
        *(float4*)&g_z[i] = make_float4(0.f, 0.f, 0.f, 0.f);
        *(float4*)&g_num[i] = make_float4(0.f, 0.f, 0.f, 0.f);
    }
    if (bid < C) {
        int r = bid;
        if (threadIdx.x < C) {
            int c = threadIdx.x;
            float aq = 0.f, ak = 0.f;
            for (int j = 0; j < C; j++) {
                float w = att_w1[j * C + c];
                aq += Wdst[r * C + j] * w;
                ak += Wsrc[r * C + j] * w;
            }
            g_Wq[r * C + c] = aq;
            g_Wk[r * C + c] = ak;
        } else {
            int nn = threadIdx.x - C;
            g_B1h[nn * C + r] = __float2half_rn(w1[r * C + nn]);
            g_B2h[nn * C + r] = __float2half_rn(w2[r * C + nn]);
            g_B3h[nn * C + r] = __float2half_rn(w3[r * C + nn]);
        }
    }
}

// ---------------- launch 2: node12 (blocks < nb) + scatter (tail blocks) ----------------
#define SZ12 213504
__global__ void __launch_bounds__(256, 1)
node12_kernel(const float* __restrict__ x, const float* __restrict__ pos,
              const float* __restrict__ W_in, const float* __restrict__ b_in,
              const float* __restrict__ pos_w1, const float* __restrict__ W_lin,
              int n, int nb, long long E) {
    int tid = threadIdx.x;
    if (blockIdx.x >= nb) {
        int sblocks = gridDim.x - nb;
        for (long long i = (long long)(blockIdx.x - nb) * 256 + tid; i < E;
             i += (long long)sblocks * 256) {
            int d = g_dst[i];
            int p = atomicAdd(&g_cnt[d], 1);
            g_src2[p] = g_src[i];
            g_dst2[p] = d;
        }
        return;
    }

    extern __shared__ float sm[];
    float* W0 = sm;
    float* W1 = sm + 16384;
    float* W2 = sm + 32768;
    float* sx = sm + 32768;
    float* sp = sm + 36864;
    float* sh = sm + 49152;
    float* sb = sm + 53248;

    for (int i = tid; i < C * C; i += 256) {
        W0[i] = W_in[i];
        W1[i] = pos_w1[i];
    }
    if (tid < C) sb[tid] = b_in[tid];
    __syncthreads();

    int cg = tid & 31, ng = tid >> 5;
    int nbase = blockIdx.x * 32 + ng * 4;

#pragma unroll
    for (int i = 0; i < 4; i++) {
        int nn = nbase + i;
        if (nn < n) {
            ((float4*)&sx[(ng * 4 + i) * C])[cg] = ((const float4*)&x[(size_t)nn * C])[cg];
            ((float4*)&sp[(ng * 4 + i) * C])[cg] = ((const float4*)&pos[(size_t)nn * C])[cg];
        }
    }
    __syncwarp();

    {
        float4 ah[4], ap[4];
#pragma unroll
        for (int i = 0; i < 4; i++) {
            ah[i] = make_float4(0.f, 0.f, 0.f, 0.f);
            ap[i] = make_float4(0.f, 0.f, 0.f, 0.f);
        }
#pragma unroll 2
        for (int k = 0; k < C; k++) {
            float4 wi = ((float4*)W0)[k * 32 + cg];
            float4 wp = ((float4*)W1)[k * 32 + cg];
#pragma unroll
            for (int i = 0; i < 4; i++) {
                float xv = sx[(ng * 4 + i) * C + k];
                float pv = sp[(ng * 4 + i) * C + k];
                ah[i].x += xv * wi.x; ah[i].y += xv * wi.y;
                ah[i].z += xv * wi.z; ah[i].w += xv * wi.w;
                ap[i].x += pv * wp.x; ap[i].y += pv * wp.y;
                ap[i].z += pv * wp.z; ap[i].w += pv * wp.w;
            }
        }
        float4 bv = ((float4*)sb)[cg];
#pragma unroll
        for (int i = 0; i < 4; i++) {
            int nn = nbase + i;
            float4 hv;
            hv.x = fmaxf(ah[i].x + bv.x, 0.f);
            hv.y = fmaxf(ah[i].y + bv.y, 0.f);
            hv.z = fmaxf(ah[i].z + bv.z, 0.f);
            hv.w = fmaxf(ah[i].w + bv.w, 0.f);
            ((float4*)&sh[(ng * 4 + i) * C])[cg] = hv;
            if (nn < n) ((float4*)&g_P1[(size_t)nn * C])[cg] = ap[i];
        }
    }
    __syncthreads();

    for (int i = tid; i < C * C; i += 256) {
        W0[i] = W_lin[i];
        W1[i] = g_Wq[i];
        W2[i] = g_Wk[i];
    }
    __syncthreads();

    float4 av[4], aq[4], ak[4];
#pragma unroll
    for (int i = 0; i < 4; i++) {
        av[i] = make_float4(0.f, 0.f, 0.f, 0.f);
        aq[i] = make_float4(0.f, 0.f, 0.f, 0.f);
        ak[i] = make_float4(0.f, 0.f, 0.f, 0.f);
    }
#pragma unroll 2
    for (int k = 0; k < C; k++) {
        float4 wl = ((float4*)W0)[k * 32 + cg];
        float4 wq = ((float4*)W1)[k * 32 + cg];
        float4 wk = ((float4*)W2)[k * 32 + cg];
#pragma unroll
        for (int i = 0; i < 4; i++) {
            float hv = sh[(ng * 4 + i) * C + k];
            av[i].x += hv * wl.x; av[i].y += hv * wl.y; av[i].z += hv * wl.z; av[i].w += hv * wl.w;
            aq[i].x += hv * wq.x; aq[i].y += hv * wq.y; aq[i].z += hv * wq.z; aq[i].w += hv * wq.w;
            ak[i].x += hv * wk.x; ak[i].y += hv * wk.y; ak[i].z += hv * wk.z; ak[i].w += hv * wk.w;
        }
    }
#pragma unroll
    for (int i = 0; i < 4; i++) {
        int nn = nbase + i;
        if (nn < n) {
            ((float4*)&g_v[(size_t)nn * C])[cg] = av[i];
            ((float4*)&g_QK[(size_t)nn * C])[cg] = aq[i];
            ((float4*)&g_KK[(size_t)nn * C])[cg] = ak[i];
        }
    }
}

// ---------------- full-block segment reduce ----------------
__device__ __forceinline__ void seg_reduce2(char* smem, const int* sDst, float* gbase,
                                            int tid) {
    int p = tid & 31;
    int hf = (tid >> 5) & 1;
    int seg = tid >> 6;
    int e0 = seg * 16;
    int chg = hf * 64 + p * 2;
    int bufoff = hf ? OFF_A0 : OFF_S2;
    float2 s = make_float2(0.f, 0.f);
    int cur = sDst[e0];
#pragma unroll 4
    for (int i = 0; i < 16; i++) {
        int e = e0 + i;
        int d = sDst[e];
        if (d != cur) {
            if (cur >= 0) atomicAdd((float2*)(gbase + (size_t)cur * C + chg), s);
            s.x = 0.f; s.y = 0.f;
            cur = d;
        }
        float2 v = *(float2*)(smem + bufoff + e * ROWB + p * 8);
        s.x += v.x; s.y += v.y;
    }
    if (cur >= 0) atomicAdd((float2*)(gbase + (size_t)cur * C + chg), s);
}

// ---------------- launch 3: tensor-core edge kernel, 2 CTAs/SM ----------------
// B fragments hoisted to registers PER GEMM (16 regs live, no spills, L1-hot loads).
__global__ void __launch_bounds__(512, 2)
edge_mma_kernel(long long E,
                const float* __restrict__ pos_b1, const float* __restrict__ pos_b2,
                const float* __restrict__ att_b1, const float* __restrict__ att_b2) {
    extern __shared__ char smem[];
    uint32_t sbase = smem_u32(smem);
    int tid = threadIdx.x, wid = tid >> 5, lane = tid & 31;

    const int nbw = wid * 8;
    const int qr = lane >> 2;
    const int qc = 2 * (lane & 3);
    const int lr = lane & 7;
    const int lg = lane >> 3;
    const int cb = nbw + qc;
    const int hf = wid >> 3;
    const int cbl = cb - hf * 64;
    const int bufoff = hf ? OFF_A0 : OFF_S2;
    // per-thread B-fragment base offset (halfs): row n = nbw + lane/4, col k = 2*(lane%4)
    const int bofs = (nbw + (lane >> 2)) * C + 2 * (lane & 3);

    float* sBias = (float*)(smem + OFF_BIAS);
    if (tid < C) {
        sBias[tid] = pos_b1[tid];
        sBias[C + tid] = pos_b2[tid];
        sBias[2 * C + tid] = att_b1[tid];
        sBias[3 * C + tid] = att_b2[tid];
    }
    __syncthreads();

    int* sSrc = (int*)(smem + OFF_IDX);
    int* sDst = sSrc + 128;

    float acc[8][4];

    for (long long tile = blockIdx.x; tile * 128 < E; tile += gridDim.x) {
        long long ebase = tile * 128;
        int nidx = 0;
        long long nb = ebase + (long long)gridDim.x * 128;
        if (tid < 128) {
            sSrc[tid] = (ebase + tid < E) ? g_src2[ebase + tid] : 0;
            if (nb + tid < E) nidx = g_src2[nb + tid];
        } else if (tid < 256) {
            int j = tid - 128;
            sDst[j] = (ebase + j < E) ? g_dst2[ebase + j] : -1;
            if (nb + j < E) nidx = g_dst2[nb + j];
        }
        __syncthreads();

        // ---- stage G: A0 = relu(P1[dst]-P1[src]+pos_b1) ----
        {
            float4 bp = ((float4*)sBias)[lane];
#pragma unroll 4
            for (int i = 0; i < 8; i++) {
                int e = wid * 8 + i;
                int s = sSrc[e];
                int d = sDst[e]; if (d < 0) d = 0;
                float4 pd = ((const float4*)(g_P1 + (size_t)d * C))[lane];
                float4 ps = ((const float4*)(g_P1 + (size_t)s * C))[lane];
                __half2 h0 = __floats2half2_rn(fmaxf(pd.x - ps.x + bp.x, 0.f),
                                               fmaxf(pd.y - ps.y + bp.y, 0.f));
                __half2 h1 = __floats2half2_rn(fmaxf(pd.z - ps.z + bp.z, 0.f),
                                               fmaxf(pd.w - ps.w + bp.w, 0.f));
                uint2 m;
                m.x = *(unsigned*)&h0;
                m.y = *(unsigned*)&h1;
                *(uint2*)(smem + OFF_A0 + e * ROWB + lane * 8) = m;
            }
        }
        __syncthreads();

// B fragments hoisted to regs at GEMM entry (16 L1-hot loads), inner loop = A-ldsm + mma.
#define GEMM(W, OFFA)                                                               \
        {                                                                           \
            uint32_t bf[8][2];                                                      \
            _Pragma("unroll")                                                       \
            for (int kt = 0; kt < 8; kt++) {                                        \
                bf[kt][0] = *(const uint32_t*)((W) + bofs + kt * 16);               \
                bf[kt][1] = *(const uint32_t*)((W) + bofs + kt * 16 + 8);           \
            }                                                                       \
            _Pragma("unroll")                                                       \
            for (int mt = 0; mt < 8; mt++)                                          \
                _Pragma("unroll")                                                   \
                for (int j = 0; j < 4; j++) acc[mt][j] = 0.f;                       \
            _Pragma("unroll 2")                                                     \
            for (int kt = 0; kt < 8; kt++) {                                        \
                _Pragma("unroll")                                                   \
                for (int mt = 0; mt < 8; mt++) {                                    \
                    uint32_t a0, a1, a2, a3;                                        \
                    uint32_t ad = sbase + (OFFA) +                                  \
                                  (mt * 16 + ((lg & 1) << 3) + lr) * ROWB +         \
                                  (kt * 16 + ((lg >> 1) << 3)) * 2;                 \
                    ldsm_x4(ad, a0, a1, a2, a3);                                    \
                    mma_16816(acc[mt], a0, a1, a2, a3, bf[kt][0], bf[kt][1]);       \
                }                                                                   \
            }                                                                       \
        }

        // ===== GEMM1: A0 @ B1^T =====
        GEMM(g_B1h, OFF_A0)

        // ---- E1: delta = relu(D + pos_b2) -> A1 ----
        {
            float b0 = sBias[C + cb], b1 = sBias[C + cb + 1];
#pragma unroll
            for (int mt = 0; mt < 8; mt++) {
                int r0 = mt * 16 + qr, r1 = r0 + 8;
                __half2 h0 = __floats2half2_rn(fmaxf(acc[mt][0] + b0, 0.f),
                                               fmaxf(acc[mt][1] + b1, 0.f));
                __half2 h1 = __floats2half2_rn(fmaxf(acc[mt][2] + b0, 0.f),
                                               fmaxf(acc[mt][3] + b1, 0.f));
                *(__half2*)(smem + OFF_A1 + r0 * ROWB + cb * 2) = h0;
                *(__half2*)(smem + OFF_A1 + r1 * ROWB + cb * 2) = h1;
            }
        }
        // L2 prefetch of next tile's gather rows
        if (nb < E) {
            if (tid < 128) {
                const float* p1 = g_P1 + (size_t)nidx * C;
                const float* kk = g_KK + (size_t)nidx * C;
                const float* vv = g_v + (size_t)nidx * C;
#pragma unroll
                for (int j = 0; j < 4; j++) {
                    PF_L2(p1 + j * 32);
                    PF_L2(kk + j * 32);
                    PF_L2(vv + j * 32);
                }
            } else if (tid < 256) {
                const float* p1 = g_P1 + (size_t)nidx * C;
                const float* qk = g_QK + (size_t)nidx * C;
#pragma unroll
                for (int j = 0; j < 4; j++) {
                    PF_L2(p1 + j * 32);
                    PF_L2(qk + j * 32);
                }
            }
        }
        __syncthreads();

        // ===== GEMM2: A1 @ B2^T =====
        GEMM(g_B2h, OFF_A1)
        __syncthreads();

        // ---- E2: t2 = relu(QK[dst]-KK[src] + D + att_b1) -> A0 ----
        {
            float b0 = sBias[2 * C + cb], b1 = sBias[2 * C + cb + 1];
#pragma unroll
            for (int mt = 0; mt < 8; mt++) {
                {
                    int r0 = mt * 16 + qr;
                    int d0i = sDst[r0]; if (d0i < 0) d0i = 0;
                    int s0i = sSrc[r0];
                    float2 q = *(const float2*)(g_QK + (size_t)d0i * C + cb);
                    float2 k = *(const float2*)(g_KK + (size_t)s0i * C + cb);
                    __half2 h = __floats2half2_rn(fmaxf(q.x - k.x + acc[mt][0] + b0, 0.f),
                                                  fmaxf(q.y - k.y + acc[mt][1] + b1, 0.f));
                    *(__half2*)(smem + OFF_A0 + r0 * ROWB + cb * 2) = h;
                }
                {
                    int r1 = mt * 16 + qr + 8;
                    int d1i = sDst[r1]; if (d1i < 0) d1i = 0;
                    int s1i = sSrc[r1];
                    float2 q = *(const float2*)(g_QK + (size_t)d1i * C + cb);
                    float2 k = *(const float2*)(g_KK + (size_t)s1i * C + cb);
                    __half2 h = __floats2half2_rn(fmaxf(q.x - k.x + acc[mt][2] + b0, 0.f),
                                                  fmaxf(q.y - k.y + acc[mt][3] + b1, 0.f));
                    *(__half2*)(smem + OFF_A0 + r1 * ROWB + cb * 2) = h;
                }
            }
        }
        __syncthreads();

        // ===== GEMM3: A0(t2) @ B3^T =====
        GEMM(g_B3h, OFF_A0)
        __syncthreads();   // all A0 reads done before staging reuse

        // ---- ez = exp(relu(D + att_b2)) in place ----
        {
            float b0 = sBias[3 * C + cb], b1 = sBias[3 * C + cb + 1];
#pragma unroll
            for (int mt = 0; mt < 8; mt++) {
                acc[mt][0] = __expf(fmaxf(acc[mt][0] + b0, 0.f));
                acc[mt][1] = __expf(fmaxf(acc[mt][1] + b1, 0.f));
                acc[mt][2] = __expf(fmaxf(acc[mt][2] + b0, 0.f));
                acc[mt][3] = __expf(fmaxf(acc[mt][3] + b1, 0.f));
            }
        }

        // ---- stage nm = ez*(v[src]+delta) ----
#pragma unroll
        for (int mt = 0; mt < 8; mt++) {
            {
                int r0 = mt * 16 + qr;
                int s0i = sSrc[r0];
                float2 v = *(const float2*)(g_v + (size_t)s0i * C + cb);
                float2 f = __half22float2(*(__half2*)(smem + OFF_A1 + r0 * ROWB + cb * 2));
                *(float2*)(smem + bufoff + r0 * ROWB + cbl * 4) =
                    make_float2(acc[mt][0] * (v.x + f.x), acc[mt][1] * (v.y + f.y));
            }
            {
                int r1 = mt * 16 + qr + 8;
                int s1i = sSrc[r1];
                float2 v = *(const float2*)(g_v + (size_t)s1i * C + cb);
                float2 f = __half22float2(*(__half2*)(smem + OFF_A1 + r1 * ROWB + cb * 2));
                *(float2*)(smem + bufoff + r1 * ROWB + cbl * 4) =
                    make_float2(acc[mt][2] * (v.x + f.x), acc[mt][3] * (v.y + f.y));
            }
        }
        __syncthreads();
        seg_reduce2(smem, sDst, g_num, tid);
        __syncthreads();

        // ---- stage ez ----
#pragma unroll
        for (int mt = 0; mt < 8; mt++) {
            int r0 = mt * 16 + qr, r1 = r0 + 8;
            *(float2*)(smem + bufoff + r0 * ROWB + cbl * 4) =
                make_float2(acc[mt][0], acc[mt][1]);
            *(float2*)(smem + bufoff + r1 * ROWB + cbl * 4) =
                make_float2(acc[mt][2], acc[mt][3]);
        }
        __syncthreads();
        seg_reduce2(smem, sDst, g_z, tid);
        __syncthreads();
    }
}

// ---------------- launch 4: out kernel (re-zeroes g_cnt) ----------------
#define SZO2 ((C * C + 32 * C + C) * 4)
__global__ void __launch_bounds__(256, 2)
out_kernel(const float* __restrict__ W_out, const float* __restrict__ b_out,
           float* __restrict__ out, int n) {
    extern __shared__ float sm[];
    float* sW = sm;
    float* srow = sm + C * C;
    float* sb = sm + C * C + 32 * C;

    int tid = threadIdx.x;
    for (int i = tid; i < C * C; i += 256) sW[i] = W_out[i];
    if (tid < C) sb[tid] = b_out[tid];
    for (int i = blockIdx.x * 256 + tid; i < n; i += gridDim.x * 256) g_cnt[i] = 0;
    __syncthreads();

    int cg = tid & 31, ng = tid >> 5;
    int nbase = blockIdx.x * 32 + ng * 4;
#pragma unroll
    for (int i = 0; i < 4; i++) {
        int nn = nbase + i;
        if (nn < n) {
            float4 nm = ((const float4*)&g_num[(size_t)nn * C])[cg];
            float4 zz = ((const float4*)&g_z[(size_t)nn * C])[cg];
            float4 ag;
            ag.x = nm.x / (zz.x + 1e-16f);
            ag.y = nm.y / (zz.y + 1e-16f);
            ag.z = nm.z / (zz.z + 1e-16f);
            ag.w = nm.w / (zz.w + 1e-16f);
            ((float4*)&srow[(ng * 4 + i) * C])[cg] = ag;
        } else {
            ((float4*)&srow[(ng * 4 + i) * C])[cg] = make_float4(0.f, 0.f, 0.f, 0.f);
        }
    }
    __syncwarp();

    float4 acc[4];
#pragma unroll
    for (int i = 0; i < 4; i++) acc[i] = make_float4(0.f, 0.f, 0.f, 0.f);
#pragma unroll 2
    for (int k = 0; k < C; k++) {
        float4 w = ((float4*)sW)[k * 32 + cg];
#pragma unroll
        for (int i = 0; i < 4; i++) {
            float av = srow[(ng * 4 + i) * C + k];
            acc[i].x += av * w.x; acc[i].y += av * w.y;
            acc[i].z += av * w.z; acc[i].w += av * w.w;
        }
    }
    float4 bv = ((float4*)sb)[cg];
#pragma unroll
    for (int i = 0; i < 4; i++) {
        int nn = nbase + i;
        if (nn < n) {
            float4 ov;
            ov.x = fmaxf(acc[i].x + bv.x, 0.f);
            ov.y = fmaxf(acc[i].y + bv.y, 0.f);
            ov.z = fmaxf(acc[i].z + bv.z, 0.f);
            ov.w = fmaxf(acc[i].w + bv.w, 0.f);
            ((float4*)&out[(size_t)nn * C])[cg] = ov;
        }
    }
}

// ---------------- launch ----------------
extern "C" void kernel_launch(void* const* d_in, const int* in_sizes, int n_in,
                              void* d_out, int out_size) {
    const float* x = (const float*)d_in[0];
    const float* pos = (const float*)d_in[1];
    const void* ei = d_in[2];
    const float* W_in = (const float*)d_in[3];
    const float* b_in = (const float*)d_in[4];
    const float* W_lin = (const float*)d_in[5];
    const float* W_src = (const float*)d_in[6];
    const float* W_dst = (const float*)d_in[7];
    const float* pos_w1 = (const float*)d_in[8];
    const float* pos_b1 = (const float*)d_in[9];
    const float* pos_w2 = (const float*)d_in[10];
    const float* pos_b2 = (const float*)d_in[11];
    const float* att_w1 = (const float*)d_in[12];
    const float* att_b1 = (const float*)d_in[13];
    const float* att_w2 = (const float*)d_in[14];
    const float* att_b2 = (const float*)d_in[15];
    const float* W_out = (const float*)d_in[16];
    const float* b_out = (const float*)d_in[17];

    int n = in_sizes[0] / C;
    long long E = in_sizes[2] / 2;
    int eb = (int)((E + 255) / 256);

    cudaFuncSetAttribute(node12_kernel, cudaFuncAttributeMaxDynamicSharedMemorySize, SZ12);
    cudaFuncSetAttribute(edge_mma_kernel, cudaFuncAttributeMaxDynamicSharedMemorySize, SZE);
    cudaFuncSetAttribute(out_kernel, cudaFuncAttributeMaxDynamicSharedMemorySize, SZO2);

    int nb = (n + 31) / 32;

    convert_hist_kernel<<<eb, 256>>>(ei, E, n);                  // launch 0
    scan_util_kernel<<<512, 256>>>(W_dst, W_src, att_w1,
                                   pos_w2, att_w1, att_w2, n);   // launch 1
    node12_kernel<<<nb + 512, 256, SZ12>>>(x, pos, W_in, b_in, pos_w1,
                                           W_lin, n, nb, E);     // launch 2 (+scatter)
    edge_mma_kernel<<<296, 512, SZE>>>(E, pos_b1, pos_b2,
                                       att_b1, att_b2);          // launch 3 (profiled, 2 CTA/SM)
    out_kernel<<<nb, 256, SZO2>>>(W_out, b_out, (float*)d_out, n); // launch 4
}

// round 16
// speedup vs baseline: 1.0960x; 1.0960x over previous
#include <cuda_runtime.h>
#include <cuda_fp16.h>
#include <cstdint>

#define C 128
#define NMAX 50176
#define EMAX 800000

// ---------------- device scratch ----------------
__device__ float g_P1[NMAX * C];
__device__ float g_QK[NMAX * C];
__device__ float g_KK[NMAX * C];
__device__ float g_v[NMAX * C];
__device__ float g_z[NMAX * C];
__device__ float g_num[NMAX * C];
__device__ float g_Wq[C * C];
__device__ float g_Wk[C * C];
__device__ int g_src[EMAX];
__device__ int g_dst[EMAX];
__device__ int g_src2[EMAX];   // sorted by dst
__device__ int g_dst2[EMAX];
__device__ int g_cnt[NMAX];    // histogram -> cursor (re-zeroed by out_kernel)
__device__ __half g_B1h[C * C];
__device__ __half g_B2h[C * C];
__device__ __half g_B3h[C * C];

// ---------------- mma helpers ----------------
__device__ __forceinline__ uint32_t smem_u32(const void* p) {
    uint32_t a;
    asm("{ .reg .u64 t; cvta.to.shared.u64 t, %1; cvt.u32.u64 %0, t; }" : "=r"(a) : "l"(p));
    return a;
}
__device__ __forceinline__ void ldsm_x4(uint32_t addr, uint32_t& r0, uint32_t& r1,
                                        uint32_t& r2, uint32_t& r3) {
    asm volatile("ldmatrix.sync.aligned.m8n8.x4.shared.b16 {%0,%1,%2,%3}, [%4];"
                 : "=r"(r0), "=r"(r1), "=r"(r2), "=r"(r3) : "r"(addr));
}
__device__ __forceinline__ void ldsm_x2(uint32_t addr, uint32_t& r0, uint32_t& r1) {
    asm volatile("ldmatrix.sync.aligned.m8n8.x2.shared.b16 {%0,%1}, [%2];"
                 : "=r"(r0), "=r"(r1) : "r"(addr));
}
__device__ __forceinline__ void mma_16816(float* acc, uint32_t a0, uint32_t a1,
                                          uint32_t a2, uint32_t a3,
                                          uint32_t b0, uint32_t b1) {
    asm volatile(
        "mma.sync.aligned.m16n8k16.row.col.f32.f16.f16.f32 "
        "{%0,%1,%2,%3}, {%4,%5,%6,%7}, {%8,%9}, {%0,%1,%2,%3};"
        : "+f"(acc[0]), "+f"(acc[1]), "+f"(acc[2]), "+f"(acc[3])
        : "r"(a0), "r"(a1), "r"(a2), "r"(a3), "r"(b0), "r"(b1));
}
#define PF_L2(ptr) asm volatile("prefetch.global.L2 [%0];" :: "l"(ptr))

// smem layout (bytes). fp16 tiles rows padded to 272B.
// Weights pass through A0/A1/S2 transiently at kernel start (fragments -> regs),
// then regions are recycled: A0/A1 = activation tiles, S2+A0 = fp32 staging.
#define ROWB 272
#define OFF_A0 0               // 34816
#define OFF_A1 34816           // 34816
#define OFF_IDX 69632          // 1024
#define OFF_BIAS 70656         // 2048
#define OFF_S2 72704           // 34816
#define SZE 107520

// ---------------- launch 0: convert (dtype detect) + histogram ----------------
__global__ void convert_hist_kernel(const void* __restrict__ ei, long long E, int n) {
    __shared__ int s_is64;
    if (threadIdx.x == 0) {
        const long long* p = (const long long*)ei;
        int ok64 = 1;
        int lim = (E < 64) ? (int)E : 64;
        for (int i = 0; i < lim; i++) {
            long long v = p[i];
            if (v < 0 || v >= n) { ok64 = 0; break; }
        }
        s_is64 = ok64;
    }
    __syncthreads();
    long long i = (long long)blockIdx.x * blockDim.x + threadIdx.x;
    if (i >= E) return;
    int s, d;
    if (s_is64) {
        const long long* p = (const long long*)ei;
        s = (int)p[i];
        d = (int)p[E + i];
    } else {
        const int* p = (const int*)ei;
        s = p[i];
        d = p[E + i];
    }
    g_src[i] = s;
    g_dst[i] = d;
    atomicAdd(&g_cnt[d], 1);
}

// ---------------- launch 1: scan (block 0) + util (blocks 1..) ----------------
__global__ void scan_util_kernel(const float* __restrict__ Wdst, const float* __restrict__ Wsrc,
                                 const float* __restrict__ att_w1,
                                 const float* __restrict__ w1, const float* __restrict__ w2,
                                 const float* __restrict__ w3, int n) {
    if (blockIdx.x == 0) {
        __shared__ int part[256];
        int t = threadIdx.x;
        int chunk = (n + 255) / 256;
        int lo = t * chunk;
        int hi = lo + chunk; if (hi > n) hi = n;
        int s = 0;
        for (int i = lo; i < hi; i++) s += g_cnt[i];
        part[t] = s;
        __syncthreads();
        for (int d = 1; d < 256; d <<= 1) {
            int v = (t >= d) ? part[t - d] : 0;
            __syncthreads();
            part[t] += v;
            __syncthreads();
        }
        int excl = (t == 0) ? 0 : part[t - 1];
        for (int i = lo; i < hi; i++) {
            int c = g_cnt[i];
            g_cnt[i] = excl;
            excl += c;
        }
        return;
    }
    int bid = blockIdx.x - 1;
    int total = n * C;
    for (int i = (bid * 256 + threadIdx.x) * 4; i < total; i += 511 * 256 * 4) {
        *(float4*)&g_z[i] = make_float4(0.f, 0.f, 0.f, 0.f);
        *(float4*)&g_num[i] = make_float4(0.f, 0.f, 0.f, 0.f);
    }
    if (bid < C) {
        int r = bid;
        if (threadIdx.x < C) {
            int c = threadIdx.x;
            float aq = 0.f, ak = 0.f;
            for (int j = 0; j < C; j++) {
                float w = att_w1[j * C + c];
                aq += Wdst[r * C + j] * w;
                ak += Wsrc[r * C + j] * w;
            }
            g_Wq[r * C + c] = aq;
            g_Wk[r * C + c] = ak;
        } else {
            int nn = threadIdx.x - C;
            g_B1h[nn * C + r] = __float2half_rn(w1[r * C + nn]);
            g_B2h[nn * C + r] = __float2half_rn(w2[r * C + nn]);
            g_B3h[nn * C + r] = __float2half_rn(w3[r * C + nn]);
        }
    }
}

// ---------------- launch 2: node12 (blocks < nb) + scatter (tail blocks) ----------------
#define SZ12 213504
__global__ void __launch_bounds__(256, 1)
node12_kernel(const float* __restrict__ x, const float* __restrict__ pos,
              const float* __restrict__ W_in, const float* __restrict__ b_in,
              const float* __restrict__ pos_w1, const float* __restrict__ W_lin,
              int n, int nb, long long E) {
    int tid = threadIdx.x;
    if (blockIdx.x >= nb) {
        int sblocks = gridDim.x - nb;
        for (long long i = (long long)(blockIdx.x - nb) * 256 + tid; i < E;
             i += (long long)sblocks * 256) {
            int d = g_dst[i];
            int p = atomicAdd(&g_cnt[d], 1);
            g_src2[p] = g_src[i];
            g_dst2[p] = d;
        }
        return;
    }

    extern __shared__ float sm[];
    float* W0 = sm;
    float* W1 = sm + 16384;
    float* W2 = sm + 32768;
    float* sx = sm + 32768;
    float* sp = sm + 36864;
    float* sh = sm + 49152;
    float* sb = sm + 53248;

    for (int i = tid; i < C * C; i += 256) {
        W0[i] = W_in[i];
        W1[i] = pos_w1[i];
    }
    if (tid < C) sb[tid] = b_in[tid];
    __syncthreads();

    int cg = tid & 31, ng = tid >> 5;
    int nbase = blockIdx.x * 32 + ng * 4;

#pragma unroll
    for (int i = 0; i < 4; i++) {
        int nn = nbase + i;
        if (nn < n) {
            ((float4*)&sx[(ng * 4 + i) * C])[cg] = ((const float4*)&x[(size_t)nn * C])[cg];
            ((float4*)&sp[(ng * 4 + i) * C])[cg] = ((const float4*)&pos[(size_t)nn * C])[cg];
        }
    }
    __syncwarp();

    {
        float4 ah[4], ap[4];
#pragma unroll
        for (int i = 0; i < 4; i++) {
            ah[i] = make_float4(0.f, 0.f, 0.f, 0.f);
            ap[i] = make_float4(0.f, 0.f, 0.f, 0.f);
        }
#pragma unroll 2
        for (int k = 0; k < C; k++) {
            float4 wi = ((float4*)W0)[k * 32 + cg];
            float4 wp = ((float4*)W1)[k * 32 + cg];
#pragma unroll
            for (int i = 0; i < 4; i++) {
                float xv = sx[(ng * 4 + i) * C + k];
                float pv = sp[(ng * 4 + i) * C + k];
                ah[i].x += xv * wi.x; ah[i].y += xv * wi.y;
                ah[i].z += xv * wi.z; ah[i].w += xv * wi.w;
                ap[i].x += pv * wp.x; ap[i].y += pv * wp.y;
                ap[i].z += pv * wp.z; ap[i].w += pv * wp.w;
            }
        }
        float4 bv = ((float4*)sb)[cg];
#pragma unroll
        for (int i = 0; i < 4; i++) {
            int nn = nbase + i;
            float4 hv;
            hv.x = fmaxf(ah[i].x + bv.x, 0.f);
            hv.y = fmaxf(ah[i].y + bv.y, 0.f);
            hv.z = fmaxf(ah[i].z + bv.z, 0.f);
            hv.w = fmaxf(ah[i].w + bv.w, 0.f);
            ((float4*)&sh[(ng * 4 + i) * C])[cg] = hv;
            if (nn < n) ((float4*)&g_P1[(size_t)nn * C])[cg] = ap[i];
        }
    }
    __syncthreads();

    for (int i = tid; i < C * C; i += 256) {
        W0[i] = W_lin[i];
        W1[i] = g_Wq[i];
        W2[i] = g_Wk[i];
    }
    __syncthreads();

    float4 av[4], aq[4], ak[4];
#pragma unroll
    for (int i = 0; i < 4; i++) {
        av[i] = make_float4(0.f, 0.f, 0.f, 0.f);
        aq[i] = make_float4(0.f, 0.f, 0.f, 0.f);
        ak[i] = make_float4(0.f, 0.f, 0.f, 0.f);
    }
#pragma unroll 2
    for (int k = 0; k < C; k++) {
        float4 wl = ((float4*)W0)[k * 32 + cg];
        float4 wq = ((float4*)W1)[k * 32 + cg];
        float4 wk = ((float4*)W2)[k * 32 + cg];
#pragma unroll
        for (int i = 0; i < 4; i++) {
            float hv = sh[(ng * 4 + i) * C + k];
            av[i].x += hv * wl.x; av[i].y += hv * wl.y; av[i].z += hv * wl.z; av[i].w += hv * wl.w;
            aq[i].x += hv * wq.x; aq[i].y += hv * wq.y; aq[i].z += hv * wq.z; aq[i].w += hv * wq.w;
            ak[i].x += hv * wk.x; ak[i].y += hv * wk.y; ak[i].z += hv * wk.z; ak[i].w += hv * wk.w;
        }
    }
#pragma unroll
    for (int i = 0; i < 4; i++) {
        int nn = nbase + i;
        if (nn < n) {
            ((float4*)&g_v[(size_t)nn * C])[cg] = av[i];
            ((float4*)&g_QK[(size_t)nn * C])[cg] = aq[i];
            ((float4*)&g_KK[(size_t)nn * C])[cg] = ak[i];
        }
    }
}

// ---------------- full-block segment reduce ----------------
__device__ __forceinline__ void seg_reduce2(char* smem, const int* sDst, float* gbase,
                                            int tid) {
    int p = tid & 31;
    int hf = (tid >> 5) & 1;
    int seg = tid >> 6;
    int e0 = seg * 16;
    int chg = hf * 64 + p * 2;
    int bufoff = hf ? OFF_A0 : OFF_S2;
    float2 s = make_float2(0.f, 0.f);
    int cur = sDst[e0];
#pragma unroll 4
    for (int i = 0; i < 16; i++) {
        int e = e0 + i;
        int d = sDst[e];
        if (d != cur) {
            if (cur >= 0) atomicAdd((float2*)(gbase + (size_t)cur * C + chg), s);
            s.x = 0.f; s.y = 0.f;
            cur = d;
        }
        float2 v = *(float2*)(smem + bufoff + e * ROWB + p * 8);
        s.x += v.x; s.y += v.y;
    }
    if (cur >= 0) atomicAdd((float2*)(gbase + (size_t)cur * C + chg), s);
}

// ---------------- launch 3: tensor-core edge kernel, 2 CTAs/SM ----------------
// R12 configuration (measured best): B fragments hoisted into registers across ALL tiles.
__global__ void __launch_bounds__(512, 2)
edge_mma_kernel(long long E,
                const float* __restrict__ pos_b1, const float* __restrict__ pos_b2,
                const float* __restrict__ att_b1, const float* __restrict__ att_b2) {
    extern __shared__ char smem[];
    uint32_t sbase = smem_u32(smem);
    int tid = threadIdx.x, wid = tid >> 5, lane = tid & 31;

    const int nbw = wid * 8;
    const int qr = lane >> 2;
    const int qc = 2 * (lane & 3);
    const int lr = lane & 7;
    const int lg = lane >> 3;
    const int cb = nbw + qc;
    const int hf = wid >> 3;
    const int cbl = cb - hf * 64;
    const int bufoff = hf ? OFF_A0 : OFF_S2;

    // ---- stage weights through A0/A1/S2, hoist fragments to registers ----
    for (int i = tid; i < C * C; i += 512) {
        int n = i >> 7, k = i & 127;
        uint32_t o = n * ROWB + k * 2;
        *(__half*)(smem + OFF_A0 + o) = g_B1h[i];
        *(__half*)(smem + OFF_A1 + o) = g_B2h[i];
        *(__half*)(smem + OFF_S2 + o) = g_B3h[i];
    }
    float* sBias = (float*)(smem + OFF_BIAS);
    if (tid < C) {
        sBias[tid] = pos_b1[tid];
        sBias[C + tid] = pos_b2[tid];
        sBias[2 * C + tid] = att_b1[tid];
        sBias[3 * C + tid] = att_b2[tid];
    }
    __syncthreads();

    uint32_t bf1[8][2], bf2[8][2], bf3[8][2];
    {
        uint32_t wcol = (nbw + lr) * ROWB + (lg & 1) * 16;
#pragma unroll
        for (int kt = 0; kt < 8; kt++) {
            ldsm_x2(sbase + OFF_A0 + wcol + kt * 32, bf1[kt][0], bf1[kt][1]);
            ldsm_x2(sbase + OFF_A1 + wcol + kt * 32, bf2[kt][0], bf2[kt][1]);
            ldsm_x2(sbase + OFF_S2 + wcol + kt * 32, bf3[kt][0], bf3[kt][1]);
        }
    }
    __syncthreads();   // fragments loaded; regions recycle as tiles/staging

    int* sSrc = (int*)(smem + OFF_IDX);
    int* sDst = sSrc + 128;

    float acc[8][4];

    for (long long tile = blockIdx.x; tile * 128 < E; tile += gridDim.x) {
        long long ebase = tile * 128;
        int nidx = 0;
        long long nb = ebase + (long long)gridDim.x * 128;
        if (tid < 128) {
            sSrc[tid] = (ebase + tid < E) ? g_src2[ebase + tid] : 0;
            if (nb + tid < E) nidx = g_src2[nb + tid];
        } else if (tid < 256) {
            int j = tid - 128;
            sDst[j] = (ebase + j < E) ? g_dst2[ebase + j] : -1;
            if (nb + j < E) nidx = g_dst2[nb + j];
        }
        __syncthreads();

        // ---- stage G: A0 = relu(P1[dst]-P1[src]+pos_b1) ----
        {
            float4 bp = ((float4*)sBias)[lane];
#pragma unroll 4
            for (int i = 0; i < 8; i++) {
                int e = wid * 8 + i;
                int s = sSrc[e];
                int d = sDst[e]; if (d < 0) d = 0;
                float4 pd = ((const float4*)(g_P1 + (size_t)d * C))[lane];
                float4 ps = ((const float4*)(g_P1 + (size_t)s * C))[lane];
                __half2 h0 = __floats2half2_rn(fmaxf(pd.x - ps.x + bp.x, 0.f),
                                               fmaxf(pd.y - ps.y + bp.y, 0.f));
                __half2 h1 = __floats2half2_rn(fmaxf(pd.z - ps.z + bp.z, 0.f),
                                               fmaxf(pd.w - ps.w + bp.w, 0.f));
                uint2 m;
                m.x = *(unsigned*)&h0;
                m.y = *(unsigned*)&h1;
                *(uint2*)(smem + OFF_A0 + e * ROWB + lane * 8) = m;
            }
        }
        __syncthreads();

// B fragments already in registers (BF): A-side ldsm only.
#define GEMM(BF, OFFA)                                                              \
        {                                                                           \
            _Pragma("unroll")                                                       \
            for (int mt = 0; mt < 8; mt++)                                          \
                _Pragma("unroll")                                                   \
                for (int j = 0; j < 4; j++) acc[mt][j] = 0.f;                       \
            _Pragma("unroll 2")                                                     \
            for (int kt = 0; kt < 8; kt++) {                                        \
                _Pragma("unroll")                                                   \
                for (int mt = 0; mt < 8; mt++) {                                    \
                    uint32_t a0, a1, a2, a3;                                        \
                    uint32_t ad = sbase + (OFFA) +                                  \
                                  (mt * 16 + ((lg & 1) << 3) + lr) * ROWB +         \
                                  (kt * 16 + ((lg >> 1) << 3)) * 2;                 \
                    ldsm_x4(ad, a0, a1, a2, a3);                                    \
                    mma_16816(acc[mt], a0, a1, a2, a3, BF[kt][0], BF[kt][1]);       \
                }                                                                   \
            }                                                                       \
        }

        // ===== GEMM1: A0 @ B1^T =====
        GEMM(bf1, OFF_A0)

        // ---- E1: delta = relu(D + pos_b2) -> A1 ----
        {
            float b0 = sBias[C + cb], b1 = sBias[C + cb + 1];
#pragma unroll
            for (int mt = 0; mt < 8; mt++) {
                int r0 = mt * 16 + qr, r1 = r0 + 8;
                __half2 h0 = __floats2half2_rn(fmaxf(acc[mt][0] + b0, 0.f),
                                               fmaxf(acc[mt][1] + b1, 0.f));
                __half2 h1 = __floats2half2_rn(fmaxf(acc[mt][2] + b0, 0.f),
                                               fmaxf(acc[mt][3] + b1, 0.f));
                *(__half2*)(smem + OFF_A1 + r0 * ROWB + cb * 2) = h0;
                *(__half2*)(smem + OFF_A1 + r1 * ROWB + cb * 2) = h1;
            }
        }
        // L2 prefetch of next tile's gather rows
        if (nb < E) {
            if (tid < 128) {
                const float* p1 = g_P1 + (size_t)nidx * C;
                const float* kk = g_KK + (size_t)nidx * C;
                const float* vv = g_v + (size_t)nidx * C;
#pragma unroll
                for (int j = 0; j < 4; j++) {
                    PF_L2(p1 + j * 32);
                    PF_L2(kk + j * 32);
                    PF_L2(vv + j * 32);
                }
            } else if (tid < 256) {
                const float* p1 = g_P1 + (size_t)nidx * C;
                const float* qk = g_QK + (size_t)nidx * C;
#pragma unroll
                for (int j = 0; j < 4; j++) {
                    PF_L2(p1 + j * 32);
                    PF_L2(qk + j * 32);
                }
            }
        }
        __syncthreads();

        // ===== GEMM2: A1 @ B2^T =====
        GEMM(bf2, OFF_A1)
        __syncthreads();

        // ---- E2: t2 = relu(QK[dst]-KK[src] + D + att_b1) -> A0 ----
        {
            float b0 = sBias[2 * C + cb], b1 = sBias[2 * C + cb + 1];
#pragma unroll
            for (int mt = 0; mt < 8; mt++) {
                {
                    int r0 = mt * 16 + qr;
                    int d0i = sDst[r0]; if (d0i < 0) d0i = 0;
                    int s0i = sSrc[r0];
                    float2 q = *(const float2*)(g_QK + (size_t)d0i * C + cb);
                    float2 k = *(const float2*)(g_KK + (size_t)s0i * C + cb);
                    __half2 h = __floats2half2_rn(fmaxf(q.x - k.x + acc[mt][0] + b0, 0.f),
                                                  fmaxf(q.y - k.y + acc[mt][1] + b1, 0.f));
                    *(__half2*)(smem + OFF_A0 + r0 * ROWB + cb * 2) = h;
                }
                {
                    int r1 = mt * 16 + qr + 8;
                    int d1i = sDst[r1]; if (d1i < 0) d1i = 0;
                    int s1i = sSrc[r1];
                    float2 q = *(const float2*)(g_QK + (size_t)d1i * C + cb);
                    float2 k = *(const float2*)(g_KK + (size_t)s1i * C + cb);
                    __half2 h = __floats2half2_rn(fmaxf(q.x - k.x + acc[mt][2] + b0, 0.f),
                                                  fmaxf(q.y - k.y + acc[mt][3] + b1, 0.f));
                    *(__half2*)(smem + OFF_A0 + r1 * ROWB + cb * 2) = h;
                }
            }
        }
        __syncthreads();

        // ===== GEMM3: A0(t2) @ B3^T =====
        GEMM(bf3, OFF_A0)
        __syncthreads();   // all A0 reads done before staging reuse

        // ---- ez = exp(relu(D + att_b2)) in place ----
        {
            float b0 = sBias[3 * C + cb], b1 = sBias[3 * C + cb + 1];
#pragma unroll
            for (int mt = 0; mt < 8; mt++) {
                acc[mt][0] = __expf(fmaxf(acc[mt][0] + b0, 0.f));
                acc[mt][1] = __expf(fmaxf(acc[mt][1] + b1, 0.f));
                acc[mt][2] = __expf(fmaxf(acc[mt][2] + b0, 0.f));
                acc[mt][3] = __expf(fmaxf(acc[mt][3] + b1, 0.f));
            }
        }

        // ---- stage nm = ez*(v[src]+delta) ----
#pragma unroll
        for (int mt = 0; mt < 8; mt++) {
            {
                int r0 = mt * 16 + qr;
                int s0i = sSrc[r0];
                float2 v = *(const float2*)(g_v + (size_t)s0i * C + cb);
                float2 f = __half22float2(*(__half2*)(smem + OFF_A1 + r0 * ROWB + cb * 2));
                *(float2*)(smem + bufoff + r0 * ROWB + cbl * 4) =
                    make_float2(acc[mt][0] * (v.x + f.x), acc[mt][1] * (v.y + f.y));
            }
            {
                int r1 = mt * 16 + qr + 8;
                int s1i = sSrc[r1];
                float2 v = *(const float2*)(g_v + (size_t)s1i * C + cb);
                float2 f = __half22float2(*(__half2*)(smem + OFF_A1 + r1 * ROWB + cb * 2));
                *(float2*)(smem + bufoff + r1 * ROWB + cbl * 4) =
                    make_float2(acc[mt][2] * (v.x + f.x), acc[mt][3] * (v.y + f.y));
            }
        }
        __syncthreads();
        seg_reduce2(smem, sDst, g_num, tid);
        __syncthreads();

        // ---- stage ez ----
#pragma unroll
        for (int mt = 0; mt < 8; mt++) {
            int r0 = mt * 16 + qr, r1 = r0 + 8;
            *(float2*)(smem + bufoff + r0 * ROWB + cbl * 4) =
                make_float2(acc[mt][0], acc[mt][1]);
            *(float2*)(smem + bufoff + r1 * ROWB + cbl * 4) =
                make_float2(acc[mt][2], acc[mt][3]);
        }
        __syncthreads();
        seg_reduce2(smem, sDst, g_z, tid);
        __syncthreads();
    }
}

// ---------------- launch 4: out kernel (re-zeroes g_cnt) ----------------
#define SZO2 ((C * C + 32 * C + C) * 4)
__global__ void __launch_bounds__(256, 2)
out_kernel(const float* __restrict__ W_out, const float* __restrict__ b_out,
           float* __restrict__ out, int n) {
    extern __shared__ float sm[];
    float* sW = sm;
    float* srow = sm + C * C;
    float* sb = sm + C * C + 32 * C;

    int tid = threadIdx.x;
    for (int i = tid; i < C * C; i += 256) sW[i] = W_out[i];
    if (tid < C) sb[tid] = b_out[tid];
    for (int i = blockIdx.x * 256 + tid; i < n; i += gridDim.x * 256) g_cnt[i] = 0;
    __syncthreads();

    int cg = tid & 31, ng = tid >> 5;
    int nbase = blockIdx.x * 32 + ng * 4;
#pragma unroll
    for (int i = 0; i < 4; i++) {
        int nn = nbase + i;
        if (nn < n) {
            float4 nm = ((const float4*)&g_num[(size_t)nn * C])[cg];
            float4 zz = ((const float4*)&g_z[(size_t)nn * C])[cg];
            float4 ag;
            ag.x = nm.x / (zz.x + 1e-16f);
            ag.y = nm.y / (zz.y + 1e-16f);
            ag.z = nm.z / (zz.z + 1e-16f);
            ag.w = nm.w / (zz.w + 1e-16f);
            ((float4*)&srow[(ng * 4 + i) * C])[cg] = ag;
        } else {
            ((float4*)&srow[(ng * 4 + i) * C])[cg] = make_float4(0.f, 0.f, 0.f, 0.f);
        }
    }
    __syncwarp();

    float4 acc[4];
#pragma unroll
    for (int i = 0; i < 4; i++) acc[i] = make_float4(0.f, 0.f, 0.f, 0.f);
#pragma unroll 2
    for (int k = 0; k < C; k++) {
        float4 w = ((float4*)sW)[k * 32 + cg];
#pragma unroll
        for (int i = 0; i < 4; i++) {
            float av = srow[(ng * 4 + i) * C + k];
            acc[i].x += av * w.x; acc[i].y += av * w.y;
            acc[i].z += av * w.z; acc[i].w += av * w.w;
        }
    }
    float4 bv = ((float4*)sb)[cg];
#pragma unroll
    for (int i = 0; i < 4; i++) {
        int nn = nbase + i;
        if (nn < n) {
            float4 ov;
            ov.x = fmaxf(acc[i].x + bv.x, 0.f);
            ov.y = fmaxf(acc[i].y + bv.y, 0.f);
            ov.z = fmaxf(acc[i].z + bv.z, 0.f);
            ov.w = fmaxf(acc[i].w + bv.w, 0.f);
            ((float4*)&out[(size_t)nn * C])[cg] = ov;
        }
    }
}

// ---------------- launch ----------------
extern "C" void kernel_launch(void* const* d_in, const int* in_sizes, int n_in,
                              void* d_out, int out_size) {
    const float* x = (const float*)d_in[0];
    const float* pos = (const float*)d_in[1];
    const void* ei = d_in[2];
    const float* W_in = (const float*)d_in[3];
    const float* b_in = (const float*)d_in[4];
    const float* W_lin = (const float*)d_in[5];
    const float* W_src = (const float*)d_in[6];
    const float* W_dst = (const float*)d_in[7];
    const float* pos_w1 = (const float*)d_in[8];
    const float* pos_b1 = (const float*)d_in[9];
    const float* pos_w2 = (const float*)d_in[10];
    const float* pos_b2 = (const float*)d_in[11];
    const float* att_w1 = (const float*)d_in[12];
    const float* att_b1 = (const float*)d_in[13];
    const float* att_w2 = (const float*)d_in[14];
    const float* att_b2 = (const float*)d_in[15];
    const float* W_out = (const float*)d_in[16];
    const float* b_out = (const float*)d_in[17];

    int n = in_sizes[0] / C;
    long long E = in_sizes[2] / 2;
    int eb = (int)((E + 255) / 256);

    cudaFuncSetAttribute(node12_kernel, cudaFuncAttributeMaxDynamicSharedMemorySize, SZ12);
    cudaFuncSetAttribute(edge_mma_kernel, cudaFuncAttributeMaxDynamicSharedMemorySize, SZE);
    cudaFuncSetAttribute(out_kernel, cudaFuncAttributeMaxDynamicSharedMemorySize, SZO2);

    int nb = (n + 31) / 32;

    convert_hist_kernel<<<eb, 256>>>(ei, E, n);                  // launch 0
    scan_util_kernel<<<512, 256>>>(W_dst, W_src, att_w1,
                                   pos_w2, att_w1, att_w2, n);   // launch 1
    node12_kernel<<<nb + 512, 256, SZ12>>>(x, pos, W_in, b_in, pos_w1,
                                           W_lin, n, nb, E);     // launch 2 (+scatter)
    edge_mma_kernel<<<592, 512, SZE>>>(E, pos_b1, pos_b2,
                                       att_b1, att_b2);          // launch 3 (queued blocks balance tail)
    out_kernel<<<nb, 256, SZO2>>>(W_out, b_out, (float*)d_out, n); // launch 4
}

// round 17
// speedup vs baseline: 1.3608x; 1.2416x over previous
#include <cuda_runtime.h>
#include <cuda_fp16.h>
#include <cstdint>

#define C 128
#define NMAX 50176
#define EMAX 800000

// ---------------- device scratch ----------------
__device__ float g_P1[NMAX * C];
__device__ float g_QK[NMAX * C];
__device__ float g_KK[NMAX * C];
__device__ float g_v[NMAX * C];
__device__ float g_z[NMAX * C];
__device__ float g_num[NMAX * C];
__device__ int g_src[EMAX];
__device__ int g_dst[EMAX];
__device__ int g_src2[EMAX];   // sorted by dst
__device__ int g_dst2[EMAX];
__device__ int g_cnt[NMAX];    // histogram -> cursor (re-zeroed by out_kernel)
// fp16 transposed weights [n][k]: edge
__device__ __half g_B1h[C * C];
__device__ __half g_B2h[C * C];
__device__ __half g_B3h[C * C];
// fp16 transposed weights: node
__device__ __half g_Binh[C * C];   // W_in^T
__device__ __half g_Bp1h[C * C];   // pos_w1^T
__device__ __half g_Blh[C * C];    // W_lin^T
__device__ __half g_Bqh[C * C];    // (W_dst@att_w1)^T
__device__ __half g_Bkh[C * C];    // (W_src@att_w1)^T

// ---------------- mma helpers ----------------
__device__ __forceinline__ uint32_t smem_u32(const void* p) {
    uint32_t a;
    asm("{ .reg .u64 t; cvta.to.shared.u64 t, %1; cvt.u32.u64 %0, t; }" : "=r"(a) : "l"(p));
    return a;
}
__device__ __forceinline__ void ldsm_x4(uint32_t addr, uint32_t& r0, uint32_t& r1,
                                        uint32_t& r2, uint32_t& r3) {
    asm volatile("ldmatrix.sync.aligned.m8n8.x4.shared.b16 {%0,%1,%2,%3}, [%4];"
                 : "=r"(r0), "=r"(r1), "=r"(r2), "=r"(r3) : "r"(addr));
}
__device__ __forceinline__ void ldsm_x2(uint32_t addr, uint32_t& r0, uint32_t& r1) {
    asm volatile("ldmatrix.sync.aligned.m8n8.x2.shared.b16 {%0,%1}, [%2];"
                 : "=r"(r0), "=r"(r1) : "r"(addr));
}
__device__ __forceinline__ void mma_16816(float* acc, uint32_t a0, uint32_t a1,
                                          uint32_t a2, uint32_t a3,
                                          uint32_t b0, uint32_t b1) {
    asm volatile(
        "mma.sync.aligned.m16n8k16.row.col.f32.f16.f16.f32 "
        "{%0,%1,%2,%3}, {%4,%5,%6,%7}, {%8,%9}, {%0,%1,%2,%3};"
        : "+f"(acc[0]), "+f"(acc[1]), "+f"(acc[2]), "+f"(acc[3])
        : "r"(a0), "r"(a1), "r"(a2), "r"(a3), "r"(b0), "r"(b1));
}
#define PF_L2(ptr) asm volatile("prefetch.global.L2 [%0];" :: "l"(ptr))

// smem layout (bytes). fp16 tiles rows padded to 272B.
#define ROWB 272
#define OFF_A0 0               // 34816
#define OFF_A1 34816           // 34816
#define OFF_IDX 69632          // 1024
#define OFF_BIAS 70656         // 2048
#define OFF_S2 72704           // 34816
#define SZE 107520
// node kernel smem
#define OFF_NB 69632           // b_in (512B)
#define SZN 70144

// ---------------- launch 0: convert (dtype detect) + histogram ----------------
__global__ void convert_hist_kernel(const void* __restrict__ ei, long long E, int n) {
    __shared__ int s_is64;
    if (threadIdx.x == 0) {
        const long long* p = (const long long*)ei;
        int ok64 = 1;
        int lim = (E < 64) ? (int)E : 64;
        for (int i = 0; i < lim; i++) {
            long long v = p[i];
            if (v < 0 || v >= n) { ok64 = 0; break; }
        }
        s_is64 = ok64;
    }
    __syncthreads();
    long long i = (long long)blockIdx.x * blockDim.x + threadIdx.x;
    if (i >= E) return;
    int s, d;
    if (s_is64) {
        const long long* p = (const long long*)ei;
        s = (int)p[i];
        d = (int)p[E + i];
    } else {
        const int* p = (const int*)ei;
        s = p[i];
        d = p[E + i];
    }
    g_src[i] = s;
    g_dst[i] = d;
    atomicAdd(&g_cnt[d], 1);
}

// ---------------- launch 1: scan (block 0) + util (blocks 1..) ----------------
__global__ void scan_util_kernel(const float* __restrict__ Wdst, const float* __restrict__ Wsrc,
                                 const float* __restrict__ att_w1,
                                 const float* __restrict__ w1, const float* __restrict__ w2,
                                 const float* __restrict__ w3,
                                 const float* __restrict__ W_in,
                                 const float* __restrict__ pos_w1,
                                 const float* __restrict__ W_lin, int n) {
    if (blockIdx.x == 0) {
        __shared__ int part[256];
        int t = threadIdx.x;
        int chunk = (n + 255) / 256;
        int lo = t * chunk;
        int hi = lo + chunk; if (hi > n) hi = n;
        int s = 0;
        for (int i = lo; i < hi; i++) s += g_cnt[i];
        part[t] = s;
        __syncthreads();
        for (int d = 1; d < 256; d <<= 1) {
            int v = (t >= d) ? part[t - d] : 0;
            __syncthreads();
            part[t] += v;
            __syncthreads();
        }
        int excl = (t == 0) ? 0 : part[t - 1];
        for (int i = lo; i < hi; i++) {
            int c = g_cnt[i];
            g_cnt[i] = excl;
            excl += c;
        }
        return;
    }
    int bid = blockIdx.x - 1;
    int total = n * C;
    for (int i = (bid * 256 + threadIdx.x) * 4; i < total; i += 511 * 256 * 4) {
        *(float4*)&g_z[i] = make_float4(0.f, 0.f, 0.f, 0.f);
        *(float4*)&g_num[i] = make_float4(0.f, 0.f, 0.f, 0.f);
    }
    if (bid < C) {
        int r = bid;  // k-index of original weight row
        if (threadIdx.x < C) {
            int c = threadIdx.x;
            float aq = 0.f, ak = 0.f;
            for (int j = 0; j < C; j++) {
                float w = att_w1[j * C + c];
                aq += Wdst[r * C + j] * w;
                ak += Wsrc[r * C + j] * w;
            }
            g_Bqh[c * C + r] = __float2half_rn(aq);
            g_Bkh[c * C + r] = __float2half_rn(ak);
        } else {
            int nn = threadIdx.x - C;
            g_B1h[nn * C + r] = __float2half_rn(w1[r * C + nn]);
            g_B2h[nn * C + r] = __float2half_rn(w2[r * C + nn]);
            g_B3h[nn * C + r] = __float2half_rn(w3[r * C + nn]);
            g_Binh[nn * C + r] = __float2half_rn(W_in[r * C + nn]);
            g_Bp1h[nn * C + r] = __float2half_rn(pos_w1[r * C + nn]);
            g_Blh[nn * C + r] = __float2half_rn(W_lin[r * C + nn]);
        }
    }
}

// ---------------- launch 2: tensor-core node kernel + scatter (tail blocks) ----------------
// Blocks [0, nodeBlocks): 128-node tiles; blocks >= nodeBlocks: counting-sort scatter.
__global__ void __launch_bounds__(512, 2)
node_mma_kernel(const float* __restrict__ x, const float* __restrict__ pos,
                const float* __restrict__ b_in, int n, int nodeBlocks, long long E) {
    int tid = threadIdx.x;
    if (blockIdx.x >= nodeBlocks) {
        int sblocks = gridDim.x - nodeBlocks;
        for (long long i = (long long)(blockIdx.x - nodeBlocks) * 512 + tid; i < E;
             i += (long long)sblocks * 512) {
            int d = g_dst[i];
            int p = atomicAdd(&g_cnt[d], 1);
            g_src2[p] = g_src[i];
            g_dst2[p] = d;
        }
        return;
    }

    extern __shared__ char smem[];
    uint32_t sbase = smem_u32(smem);
    int wid = tid >> 5, lane = tid & 31;

    const int nbw = wid * 8;
    const int qr = lane >> 2;
    const int qc = 2 * (lane & 3);
    const int lr = lane & 7;
    const int lg = lane >> 3;
    const int cb = nbw + qc;
    const int bofs = (nbw + (lane >> 2)) * C + 2 * (lane & 3);

    float* sB = (float*)(smem + OFF_NB);
    if (tid < C) sB[tid] = b_in[tid];
    __syncthreads();

    float acc[8][4];

// gmem-B GEMM (weights L1-hot): per-kt u32 loads, A from smem via ldsm.
#define GEMMG(W, OFFA)                                                              \
        {                                                                           \
            _Pragma("unroll")                                                       \
            for (int mt = 0; mt < 8; mt++)                                          \
                _Pragma("unroll")                                                   \
                for (int j = 0; j < 4; j++) acc[mt][j] = 0.f;                       \
            _Pragma("unroll 2")                                                     \
            for (int kt = 0; kt < 8; kt++) {                                        \
                uint32_t b0 = *(const uint32_t*)((W) + bofs + kt * 16);             \
                uint32_t b1 = *(const uint32_t*)((W) + bofs + kt * 16 + 8);         \
                _Pragma("unroll")                                                   \
                for (int mt = 0; mt < 8; mt++) {                                    \
                    uint32_t a0, a1, a2, a3;                                        \
                    uint32_t ad = sbase + (OFFA) +                                  \
                                  (mt * 16 + ((lg & 1) << 3) + lr) * ROWB +         \
                                  (kt * 16 + ((lg >> 1) << 3)) * 2;                 \
                    ldsm_x4(ad, a0, a1, a2, a3);                                    \
                    mma_16816(acc[mt], a0, a1, a2, a3, b0, b1);                     \
                }                                                                   \
            }                                                                       \
        }

// store acc (fp32) to node-major gmem array
#define STORE_OUT(G)                                                                \
        {                                                                           \
            _Pragma("unroll")                                                       \
            for (int mt = 0; mt < 8; mt++) {                                        \
                int r0 = mt * 16 + qr;                                              \
                int n0 = base + r0;                                                 \
                if (n0 < n)                                                         \
                    *(float2*)((G) + (size_t)n0 * C + cb) =                         \
                        make_float2(acc[mt][0], acc[mt][1]);                        \
                int n1 = n0 + 8;                                                    \
                if (n1 < n)                                                         \
                    *(float2*)((G) + (size_t)n1 * C + cb) =                         \
                        make_float2(acc[mt][2], acc[mt][3]);                        \
            }                                                                       \
        }

    int ntiles = (n + 127) / 128;
    for (int tile = blockIdx.x; tile < ntiles; tile += nodeBlocks) {
        int base = tile * 128;

        // ---- load x rows -> A0 fp16 ----
#pragma unroll 4
        for (int i = 0; i < 8; i++) {
            int row = wid * 8 + i;
            int nd = base + row; if (nd >= n) nd = 0;
            float4 xv = ((const float4*)(x + (size_t)nd * C))[lane];
            __half2 h0 = __floats2half2_rn(xv.x, xv.y);
            __half2 h1 = __floats2half2_rn(xv.z, xv.w);
            uint2 m;
            m.x = *(unsigned*)&h0;
            m.y = *(unsigned*)&h1;
            *(uint2*)(smem + OFF_A0 + row * ROWB + lane * 8) = m;
        }
        __syncthreads();

        // ---- h = relu(x@W_in + b_in) -> A1 fp16 ----
        GEMMG(g_Binh, OFF_A0)
        {
            float b0 = sB[cb], b1 = sB[cb + 1];
#pragma unroll
            for (int mt = 0; mt < 8; mt++) {
                int r0 = mt * 16 + qr, r1 = r0 + 8;
                __half2 h0 = __floats2half2_rn(fmaxf(acc[mt][0] + b0, 0.f),
                                               fmaxf(acc[mt][1] + b1, 0.f));
                __half2 h1 = __floats2half2_rn(fmaxf(acc[mt][2] + b0, 0.f),
                                               fmaxf(acc[mt][3] + b1, 0.f));
                *(__half2*)(smem + OFF_A1 + r0 * ROWB + cb * 2) = h0;
                *(__half2*)(smem + OFF_A1 + r1 * ROWB + cb * 2) = h1;
            }
        }
        __syncthreads();   // all warps done reading A0 (GEMM) before pos overwrites it

        // ---- load pos rows -> A0 fp16 ----
#pragma unroll 4
        for (int i = 0; i < 8; i++) {
            int row = wid * 8 + i;
            int nd = base + row; if (nd >= n) nd = 0;
            float4 pv = ((const float4*)(pos + (size_t)nd * C))[lane];
            __half2 h0 = __floats2half2_rn(pv.x, pv.y);
            __half2 h1 = __floats2half2_rn(pv.z, pv.w);
            uint2 m;
            m.x = *(unsigned*)&h0;
            m.y = *(unsigned*)&h1;
            *(uint2*)(smem + OFF_A0 + row * ROWB + lane * 8) = m;
        }
        __syncthreads();   // covers pos->A0 writes and h->A1 writes

        // ---- P1 = pos@pos_w1 ----
        GEMMG(g_Bp1h, OFF_A0)
        STORE_OUT(g_P1)

        // ---- v = h@W_lin ----
        GEMMG(g_Blh, OFF_A1)
        STORE_OUT(g_v)

        // ---- QK = h@Wq ----
        GEMMG(g_Bqh, OFF_A1)
        STORE_OUT(g_QK)

        // ---- KK = h@Wk ----
        GEMMG(g_Bkh, OFF_A1)
        STORE_OUT(g_KK)

        __syncthreads();   // all A0/A1 readers done before next tile overwrites
    }
}

// ---------------- full-block segment reduce ----------------
__device__ __forceinline__ void seg_reduce2(char* smem, const int* sDst, float* gbase,
                                            int tid) {
    int p = tid & 31;
    int hf = (tid >> 5) & 1;
    int seg = tid >> 6;
    int e0 = seg * 16;
    int chg = hf * 64 + p * 2;
    int bufoff = hf ? OFF_A0 : OFF_S2;
    float2 s = make_float2(0.f, 0.f);
    int cur = sDst[e0];
#pragma unroll 4
    for (int i = 0; i < 16; i++) {
        int e = e0 + i;
        int d = sDst[e];
        if (d != cur) {
            if (cur >= 0) atomicAdd((float2*)(gbase + (size_t)cur * C + chg), s);
            s.x = 0.f; s.y = 0.f;
            cur = d;
        }
        float2 v = *(float2*)(smem + bufoff + e * ROWB + p * 8);
        s.x += v.x; s.y += v.y;
    }
    if (cur >= 0) atomicAdd((float2*)(gbase + (size_t)cur * C + chg), s);
}

// ---------------- launch 3: tensor-core edge kernel (R16 champion, unchanged) ----------------
__global__ void __launch_bounds__(512, 2)
edge_mma_kernel(long long E,
                const float* __restrict__ pos_b1, const float* __restrict__ pos_b2,
                const float* __restrict__ att_b1, const float* __restrict__ att_b2) {
    extern __shared__ char smem[];
    uint32_t sbase = smem_u32(smem);
    int tid = threadIdx.x, wid = tid >> 5, lane = tid & 31;

    const int nbw = wid * 8;
    const int qr = lane >> 2;
    const int qc = 2 * (lane & 3);
    const int lr = lane & 7;
    const int lg = lane >> 3;
    const int cb = nbw + qc;
    const int hf = wid >> 3;
    const int cbl = cb - hf * 64;
    const int bufoff = hf ? OFF_A0 : OFF_S2;

    for (int i = tid; i < C * C; i += 512) {
        int n = i >> 7, k = i & 127;
        uint32_t o = n * ROWB + k * 2;
        *(__half*)(smem + OFF_A0 + o) = g_B1h[i];
        *(__half*)(smem + OFF_A1 + o) = g_B2h[i];
        *(__half*)(smem + OFF_S2 + o) = g_B3h[i];
    }
    float* sBias = (float*)(smem + OFF_BIAS);
    if (tid < C) {
        sBias[tid] = pos_b1[tid];
        sBias[C + tid] = pos_b2[tid];
        sBias[2 * C + tid] = att_b1[tid];
        sBias[3 * C + tid] = att_b2[tid];
    }
    __syncthreads();

    uint32_t bf1[8][2], bf2[8][2], bf3[8][2];
    {
        uint32_t wcol = (nbw + lr) * ROWB + (lg & 1) * 16;
#pragma unroll
        for (int kt = 0; kt < 8; kt++) {
            ldsm_x2(sbase + OFF_A0 + wcol + kt * 32, bf1[kt][0], bf1[kt][1]);
            ldsm_x2(sbase + OFF_A1 + wcol + kt * 32, bf2[kt][0], bf2[kt][1]);
            ldsm_x2(sbase + OFF_S2 + wcol + kt * 32, bf3[kt][0], bf3[kt][1]);
        }
    }
    __syncthreads();

    int* sSrc = (int*)(smem + OFF_IDX);
    int* sDst = sSrc + 128;

    float acc[8][4];

    for (long long tile = blockIdx.x; tile * 128 < E; tile += gridDim.x) {
        long long ebase = tile * 128;
        int nidx = 0;
        long long nb = ebase + (long long)gridDim.x * 128;
        if (tid < 128) {
            sSrc[tid] = (ebase + tid < E) ? g_src2[ebase + tid] : 0;
            if (nb + tid < E) nidx = g_src2[nb + tid];
        } else if (tid < 256) {
            int j = tid - 128;
            sDst[j] = (ebase + j < E) ? g_dst2[ebase + j] : -1;
            if (nb + j < E) nidx = g_dst2[nb + j];
        }
        __syncthreads();

        {
            float4 bp = ((float4*)sBias)[lane];
#pragma unroll 4
            for (int i = 0; i < 8; i++) {
                int e = wid * 8 + i;
                int s = sSrc[e];
                int d = sDst[e]; if (d < 0) d = 0;
                float4 pd = ((const float4*)(g_P1 + (size_t)d * C))[lane];
                float4 ps = ((const float4*)(g_P1 + (size_t)s * C))[lane];
                __half2 h0 = __floats2half2_rn(fmaxf(pd.x - ps.x + bp.x, 0.f),
                                               fmaxf(pd.y - ps.y + bp.y, 0.f));
                __half2 h1 = __floats2half2_rn(fmaxf(pd.z - ps.z + bp.z, 0.f),
                                               fmaxf(pd.w - ps.w + bp.w, 0.f));
                uint2 m;
                m.x = *(unsigned*)&h0;
                m.y = *(unsigned*)&h1;
                *(uint2*)(smem + OFF_A0 + e * ROWB + lane * 8) = m;
            }
        }
        __syncthreads();

#define GEMM(BF, OFFA)                                                              \
        {                                                                           \
            _Pragma("unroll")                                                       \
            for (int mt = 0; mt < 8; mt++)                                          \
                _Pragma("unroll")                                                   \
                for (int j = 0; j < 4; j++) acc[mt][j] = 0.f;                       \
            _Pragma("unroll 2")                                                     \
            for (int kt = 0; kt < 8; kt++) {                                        \
                _Pragma("unroll")                                                   \
                for (int mt = 0; mt < 8; mt++) {                                    \
                    uint32_t a0, a1, a2, a3;                                        \
                    uint32_t ad = sbase + (OFFA) +                                  \
                                  (mt * 16 + ((lg & 1) << 3) + lr) * ROWB +         \
                                  (kt * 16 + ((lg >> 1) << 3)) * 2;                 \
                    ldsm_x4(ad, a0, a1, a2, a3);                                    \
                    mma_16816(acc[mt], a0, a1, a2, a3, BF[kt][0], BF[kt][1]);       \
                }                                                                   \
            }                                                                       \
        }

        GEMM(bf1, OFF_A0)

        {
            float b0 = sBias[C + cb], b1 = sBias[C + cb + 1];
#pragma unroll
            for (int mt = 0; mt < 8; mt++) {
                int r0 = mt * 16 + qr, r1 = r0 + 8;
                __half2 h0 = __floats2half2_rn(fmaxf(acc[mt][0] + b0, 0.f),
                                               fmaxf(acc[mt][1] + b1, 0.f));
                __half2 h1 = __floats2half2_rn(fmaxf(acc[mt][2] + b0, 0.f),
                                               fmaxf(acc[mt][3] + b1, 0.f));
                *(__half2*)(smem + OFF_A1 + r0 * ROWB + cb * 2) = h0;
                *(__half2*)(smem + OFF_A1 + r1 * ROWB + cb * 2) = h1;
            }
        }
        if (nb < E) {
            if (tid < 128) {
                const float* p1 = g_P1 + (size_t)nidx * C;
                const float* kk = g_KK + (size_t)nidx * C;
                const float* vv = g_v + (size_t)nidx * C;
#pragma unroll
                for (int j = 0; j < 4; j++) {
                    PF_L2(p1 + j * 32);
                    PF_L2(kk + j * 32);
                    PF_L2(vv + j * 32);
                }
            } else if (tid < 256) {
                const float* p1 = g_P1 + (size_t)nidx * C;
                const float* qk = g_QK + (size_t)nidx * C;
#pragma unroll
                for (int j = 0; j < 4; j++) {
                    PF_L2(p1 + j * 32);
                    PF_L2(qk + j * 32);
                }
            }
        }
        __syncthreads();

        GEMM(bf2, OFF_A1)
        __syncthreads();

        {
            float b0 = sBias[2 * C + cb], b1 = sBias[2 * C + cb + 1];
#pragma unroll
            for (int mt = 0; mt < 8; mt++) {
                {
                    int r0 = mt * 16 + qr;
                    int d0i = sDst[r0]; if (d0i < 0) d0i = 0;
                    int s0i = sSrc[r0];
                    float2 q = *(const float2*)(g_QK + (size_t)d0i * C + cb);
                    float2 k = *(const float2*)(g_KK + (size_t)s0i * C + cb);
                    __half2 h = __floats2half2_rn(fmaxf(q.x - k.x + acc[mt][0] + b0, 0.f),
                                                  fmaxf(q.y - k.y + acc[mt][1] + b1, 0.f));
                    *(__half2*)(smem + OFF_A0 + r0 * ROWB + cb * 2) = h;
                }
                {
                    int r1 = mt * 16 + qr + 8;
                    int d1i = sDst[r1]; if (d1i < 0) d1i = 0;
                    int s1i = sSrc[r1];
                    float2 q = *(const float2*)(g_QK + (size_t)d1i * C + cb);
                    float2 k = *(const float2*)(g_KK + (size_t)s1i * C + cb);
                    __half2 h = __floats2half2_rn(fmaxf(q.x - k.x + acc[mt][2] + b0, 0.f),
                                                  fmaxf(q.y - k.y + acc[mt][3] + b1, 0.f));
                    *(__half2*)(smem + OFF_A0 + r1 * ROWB + cb * 2) = h;
                }
            }
        }
        __syncthreads();

        GEMM(bf3, OFF_A0)
        __syncthreads();

        {
            float b0 = sBias[3 * C + cb], b1 = sBias[3 * C + cb + 1];
#pragma unroll
            for (int mt = 0; mt < 8; mt++) {
                acc[mt][0] = __expf(fmaxf(acc[mt][0] + b0, 0.f));
                acc[mt][1] = __expf(fmaxf(acc[mt][1] + b1, 0.f));
                acc[mt][2] = __expf(fmaxf(acc[mt][2] + b0, 0.f));
                acc[mt][3] = __expf(fmaxf(acc[mt][3] + b1, 0.f));
            }
        }

#pragma unroll
        for (int mt = 0; mt < 8; mt++) {
            {
                int r0 = mt * 16 + qr;
                int s0i = sSrc[r0];
                float2 v = *(const float2*)(g_v + (size_t)s0i * C + cb);
                float2 f = __half22float2(*(__half2*)(smem + OFF_A1 + r0 * ROWB + cb * 2));
                *(float2*)(smem + bufoff + r0 * ROWB + cbl * 4) =
                    make_float2(acc[mt][0] * (v.x + f.x), acc[mt][1] * (v.y + f.y));
            }
            {
                int r1 = mt * 16 + qr + 8;
                int s1i = sSrc[r1];
                float2 v = *(const float2*)(g_v + (size_t)s1i * C + cb);
                float2 f = __half22float2(*(__half2*)(smem + OFF_A1 + r1 * ROWB + cb * 2));
                *(float2*)(smem + bufoff + r1 * ROWB + cbl * 4) =
                    make_float2(acc[mt][2] * (v.x + f.x), acc[mt][3] * (v.y + f.y));
            }
        }
        __syncthreads();
        seg_reduce2(smem, sDst, g_num, tid);
        __syncthreads();

#pragma unroll
        for (int mt = 0; mt < 8; mt++) {
            int r0 = mt * 16 + qr, r1 = r0 + 8;
            *(float2*)(smem + bufoff + r0 * ROWB + cbl * 4) =
                make_float2(acc[mt][0], acc[mt][1]);
            *(float2*)(smem + bufoff + r1 * ROWB + cbl * 4) =
                make_float2(acc[mt][2], acc[mt][3]);
        }
        __syncthreads();
        seg_reduce2(smem, sDst, g_z, tid);
        __syncthreads();
    }
}

// ---------------- launch 4: out kernel (re-zeroes g_cnt) ----------------
#define SZO2 ((C * C + 32 * C + C) * 4)
__global__ void __launch_bounds__(256, 2)
out_kernel(const float* __restrict__ W_out, const float* __restrict__ b_out,
           float* __restrict__ out, int n) {
    extern __shared__ float sm[];
    float* sW = sm;
    float* srow = sm + C * C;
    float* sb = sm + C * C + 32 * C;

    int tid = threadIdx.x;
    for (int i = tid; i < C * C; i += 256) sW[i] = W_out[i];
    if (tid < C) sb[tid] = b_out[tid];
    for (int i = blockIdx.x * 256 + tid; i < n; i += gridDim.x * 256) g_cnt[i] = 0;
    __syncthreads();

    int cg = tid & 31, ng = tid >> 5;
    int nbase = blockIdx.x * 32 + ng * 4;
#pragma unroll
    for (int i = 0; i < 4; i++) {
        int nn = nbase + i;
        if (nn < n) {
            float4 nm = ((const float4*)&g_num[(size_t)nn * C])[cg];
            float4 zz = ((const float4*)&g_z[(size_t)nn * C])[cg];
            float4 ag;
            ag.x = nm.x / (zz.x + 1e-16f);
            ag.y = nm.y / (zz.y + 1e-16f);
            ag.z = nm.z / (zz.z + 1e-16f);
            ag.w = nm.w / (zz.w + 1e-16f);
            ((float4*)&srow[(ng * 4 + i) * C])[cg] = ag;
        } else {
            ((float4*)&srow[(ng * 4 + i) * C])[cg] = make_float4(0.f, 0.f, 0.f, 0.f);
        }
    }
    __syncwarp();

    float4 acc[4];
#pragma unroll
    for (int i = 0; i < 4; i++) acc[i] = make_float4(0.f, 0.f, 0.f, 0.f);
#pragma unroll 2
    for (int k = 0; k < C; k++) {
        float4 w = ((float4*)sW)[k * 32 + cg];
#pragma unroll
        for (int i = 0; i < 4; i++) {
            float av = srow[(ng * 4 + i) * C + k];
            acc[i].x += av * w.x; acc[i].y += av * w.y;
            acc[i].z += av * w.z; acc[i].w += av * w.w;
        }
    }
    float4 bv = ((float4*)sb)[cg];
#pragma unroll
    for (int i = 0; i < 4; i++) {
        int nn = nbase + i;
        if (nn < n) {
            float4 ov;
            ov.x = fmaxf(acc[i].x + bv.x, 0.f);
            ov.y = fmaxf(acc[i].y + bv.y, 0.f);
            ov.z = fmaxf(acc[i].z + bv.z, 0.f);
            ov.w = fmaxf(acc[i].w + bv.w, 0.f);
            ((float4*)&out[(size_t)nn * C])[cg] = ov;
        }
    }
}

// ---------------- launch ----------------
extern "C" void kernel_launch(void* const* d_in, const int* in_sizes, int n_in,
                              void* d_out, int out_size) {
    const float* x = (const float*)d_in[0];
    const float* pos = (const float*)d_in[1];
    const void* ei = d_in[2];
    const float* W_in = (const float*)d_in[3];
    const float* b_in = (const float*)d_in[4];
    const float* W_lin = (const float*)d_in[5];
    const float* W_src = (const float*)d_in[6];
    const float* W_dst = (const float*)d_in[7];
    const float* pos_w1 = (const float*)d_in[8];
    const float* pos_b1 = (const float*)d_in[9];
    const float* pos_w2 = (const float*)d_in[10];
    const float* pos_b2 = (const float*)d_in[11];
    const float* att_w1 = (const float*)d_in[12];
    const float* att_b1 = (const float*)d_in[13];
    const float* att_w2 = (const float*)d_in[14];
    const float* att_b2 = (const float*)d_in[15];
    const float* W_out = (const float*)d_in[16];
    const float* b_out = (const float*)d_in[17];

    int n = in_sizes[0] / C;
    long long E = in_sizes[2] / 2;
    int eb = (int)((E + 255) / 256);

    cudaFuncSetAttribute(node_mma_kernel, cudaFuncAttributeMaxDynamicSharedMemorySize, SZN);
    cudaFuncSetAttribute(edge_mma_kernel, cudaFuncAttributeMaxDynamicSharedMemorySize, SZE);
    cudaFuncSetAttribute(out_kernel, cudaFuncAttributeMaxDynamicSharedMemorySize, SZO2);

    int nb = (n + 31) / 32;

    convert_hist_kernel<<<eb, 256>>>(ei, E, n);                    // launch 0
    scan_util_kernel<<<512, 256>>>(W_dst, W_src, att_w1,
                                   pos_w2, att_w1, att_w2,
                                   W_in, pos_w1, W_lin, n);        // launch 1
    node_mma_kernel<<<296 + 256, 512, SZN>>>(x, pos, b_in,
                                             n, 296, E);           // launch 2 (+scatter)
    edge_mma_kernel<<<592, 512, SZE>>>(E, pos_b1, pos_b2,
                                       att_b1, att_b2);            // launch 3 (profiled)
    out_kernel<<<nb, 256, SZO2>>>(W_out, b_out, (float*)d_out, n); // launch 4
}